// round 17
// baseline (speedup 1.0000x reference)
#include <cuda_runtime.h>
#include <cuda_fp16.h>
#include <math.h>
#include <stdint.h>

#define NTOK 4096          // B*S
#define SEQ  2048
#define DIM  1024
#define NH   16
#define HD   64
#define DFF  4096
#define NQKV 3072

#define QSCALE (0.125f * 1.44269504088896f)   // 1/sqrt(64) * log2(e)

// ---------------- scratch (device globals; no allocs allowed) ----------------
__device__ float g_xn[NTOK * DIM];
__device__ float g_attn[NTOK * DIM];
__device__ float g_bqkv[NQKV];

__device__ __half g_xn_h[NTOK * DIM];
__device__ __half g_qkv_h[NTOK * NQKV];
__device__ __half g_h_h[NTOK * DIM];
__device__ __half g_ff1_h[NTOK * DFF];
__device__ __half g_wqkv_h[NQKV * DIM];
__device__ __half g_w1_h[DFF * DIM];
__device__ __half g_w2_h[DIM * DFF];

// ---------------- PTX helpers (family-portable sm_80-era ISA) ----------------
__device__ __forceinline__ uint32_t smem_u32(const void* p) {
    uint32_t a;
    asm("{ .reg .u64 t; cvta.to.shared.u64 t, %1; cvt.u32.u64 %0, t; }" : "=r"(a) : "l"(p));
    return a;
}
__device__ __forceinline__ void cp16(uint32_t dst, const void* src) {
    asm volatile("cp.async.cg.shared.global [%0], [%1], 16;" :: "r"(dst), "l"(src) : "memory");
}
__device__ __forceinline__ void cp_commit() {
    asm volatile("cp.async.commit_group;" ::: "memory");
}
template<int N> __device__ __forceinline__ void cp_wait() {
    asm volatile("cp.async.wait_group %0;" :: "n"(N) : "memory");
}
__device__ __forceinline__ void ldm_x4(uint32_t* r, uint32_t addr) {
    asm volatile("ldmatrix.sync.aligned.m8n8.x4.shared.b16 {%0,%1,%2,%3}, [%4];"
        : "=r"(r[0]), "=r"(r[1]), "=r"(r[2]), "=r"(r[3]) : "r"(addr));
}
__device__ __forceinline__ void ldm_x4t(uint32_t* r, uint32_t addr) {
    asm volatile("ldmatrix.sync.aligned.m8n8.x4.trans.shared.b16 {%0,%1,%2,%3}, [%4];"
        : "=r"(r[0]), "=r"(r[1]), "=r"(r[2]), "=r"(r[3]) : "r"(addr));
}
__device__ __forceinline__ void mma_f16(float* d, const uint32_t* a, const uint32_t* b) {
    asm volatile(
        "mma.sync.aligned.m16n8k16.row.col.f32.f16.f16.f32 "
        "{%0,%1,%2,%3}, {%4,%5,%6,%7}, {%8,%9}, {%0,%1,%2,%3};"
        : "+f"(d[0]), "+f"(d[1]), "+f"(d[2]), "+f"(d[3])
        : "r"(a[0]), "r"(a[1]), "r"(a[2]), "r"(a[3]), "r"(b[0]), "r"(b[1]));
}
__device__ __forceinline__ uint32_t pkh(float lo, float hi) {
    __half2 t = __floats2half2_rn(lo, hi);
    return *(uint32_t*)&t;
}
// 64-col fp16 tile (128B rows, 8x16B segs)
__device__ __forceinline__ uint32_t off64(int r, int s) {
    return (uint32_t)(r * 128 + ((s ^ (r & 7)) << 4));
}

// ---------------- weight prep: QKV hi (+ bias concat, Q pre-scaled) ----------------
static constexpr int WSA_QKV = NQKV * DIM / 4;
static constexpr int WSA_B   = NQKV / 4;
static constexpr int WSA_TOT = WSA_QKV + WSA_B;

__global__ __launch_bounds__(256)
void wsplit_a(const float* __restrict__ Wq, const float* __restrict__ Wk,
              const float* __restrict__ Wv, const float* __restrict__ bq,
              const float* __restrict__ bk, const float* __restrict__ bv,
              __half* __restrict__ wh, float* __restrict__ bqkv)
{
    int i = blockIdx.x * 256 + threadIdx.x;
    if (i >= WSA_TOT) return;
    if (i < WSA_QKV) {
        int e = i * 4;
        int r = e >> 10;
        float sc = 1.0f;
        const float* src;
        if (r < 1024)      { src = Wq + e;                sc = QSCALE; }
        else if (r < 2048) { src = Wk + (e - 1024*1024); }
        else               { src = Wv + (e - 2048*1024); }
        float4 v = *(const float4*)src;
        uint2 uh;
        uh.x = pkh(v.x * sc, v.y * sc);
        uh.y = pkh(v.z * sc, v.w * sc);
        *(uint2*)(wh + e) = uh;
    } else {
        int e = (i - WSA_QKV) * 4;
        #pragma unroll
        for (int j = 0; j < 4; j++) {
            int c = e + j;
            float b = (c < 1024) ? QSCALE * bq[c]
                    : (c < 2048) ? bk[c - 1024] : bv[c - 2048];
            bqkv[c] = b;
        }
    }
}

// ---------------- weight prep: W1, W2 -> fp16 ----------------
static constexpr int WSB_W1  = DFF * DIM / 4;
static constexpr int WSB_W2  = DIM * DFF / 4;
static constexpr int WSB_TOT = WSB_W1 + WSB_W2;

__global__ __launch_bounds__(256)
void wsplit_b(const float* __restrict__ W1, const float* __restrict__ W2,
              __half* __restrict__ w1h, __half* __restrict__ w2h)
{
    int i = blockIdx.x * 256 + threadIdx.x;
    if (i >= WSB_TOT) return;
    if (i < WSB_W1) {
        int e = i * 4;
        float4 v = *(const float4*)(W1 + e);
        uint2 uh;
        uh.x = pkh(v.x, v.y);
        uh.y = pkh(v.z, v.w);
        *(uint2*)(w1h + e) = uh;
    } else {
        int e = (i - WSB_W1) * 4;
        float4 v = *(const float4*)(W2 + e);
        uint2 uh;
        uh.x = pkh(v.x, v.y);
        uh.y = pkh(v.z, v.w);
        *(uint2*)(w2h + e) = uh;
    }
}

// ---------------- LayerNorm (optional residual; fp32 out + fp16 out) ----------------
__global__ __launch_bounds__(256)
void ln_kernel(const float* __restrict__ x, const float* __restrict__ res,
               const float* __restrict__ gamma, const float* __restrict__ beta,
               float* __restrict__ out, __half* __restrict__ oh)
{
    int row = blockIdx.x;
    int t = threadIdx.x;
    const float4* xr = (const float4*)(x + (size_t)row * DIM);
    float4 v = xr[t];
    if (res) {
        const float4* rr = (const float4*)(res + (size_t)row * DIM);
        float4 r = rr[t];
        v.x += r.x; v.y += r.y; v.z += r.z; v.w += r.w;
    }
    float s  = v.x + v.y + v.z + v.w;
    float s2 = v.x*v.x + v.y*v.y + v.z*v.z + v.w*v.w;
    #pragma unroll
    for (int o = 16; o > 0; o >>= 1) {
        s  += __shfl_down_sync(0xffffffffu, s,  o);
        s2 += __shfl_down_sync(0xffffffffu, s2, o);
    }
    __shared__ float ss[8], ss2[8];
    __shared__ float mean_s, rstd_s;
    if ((t & 31) == 0) { ss[t >> 5] = s; ss2[t >> 5] = s2; }
    __syncthreads();
    if (t == 0) {
        float a = 0.f, b = 0.f;
        #pragma unroll
        for (int i = 0; i < 8; i++) { a += ss[i]; b += ss2[i]; }
        float mean = a * (1.0f / DIM);
        float var  = b * (1.0f / DIM) - mean * mean;
        mean_s = mean;
        rstd_s = rsqrtf(var + 1e-5f);
    }
    __syncthreads();
    float mean = mean_s, rstd = rstd_s;
    float4 g = ((const float4*)gamma)[t];
    float4 bb = ((const float4*)beta)[t];
    float4 o4;
    o4.x = (v.x - mean) * rstd * g.x + bb.x;
    o4.y = (v.y - mean) * rstd * g.y + bb.y;
    o4.z = (v.z - mean) * rstd * g.z + bb.z;
    o4.w = (v.w - mean) * rstd * g.w + bb.w;
    size_t idx = (size_t)row * DIM + t * 4;
    if (out) *(float4*)(out + idx) = o4;
    uint2 uh;
    uh.x = pkh(o4.x, o4.y);
    uh.y = pkh(o4.z, o4.w);
    *(uint2*)(oh + idx) = uh;
}

// ---------------- 1-term fp16 GEMM: C = A @ Wh^T ----------------
// CTA 128x128, 4 warps (warp tile 64x64 -> LDSM:MMA = 0.25), 128 threads,
// K-chunk 64, 3 stages @32KB (lookahead-2, single sync/chunk), 2 CTAs/SM.
// EPI: 0 = bias -> fp16 ; 1 = bias+silu -> fp16 ; 2 = bias+res -> fp32
static constexpr uint32_t G_STAGE = 32768;    // A(16K) Bh(16K)
static constexpr int G_SMEM = 3 * G_STAGE;    // 96KB

template<int EPI>
__global__ void __launch_bounds__(128, 2)
gemm_h(const __half* __restrict__ A, const __half* __restrict__ Bh,
       const float* __restrict__ bias, const float* __restrict__ res,
       float* __restrict__ C, __half* __restrict__ Ch, int N, int K)
{
    extern __shared__ char sm[];
    const int tid = threadIdx.x;
    const int wid = tid >> 5, lane = tid & 31;
    const int bm = blockIdx.y * 128, bn = blockIdx.x * 128;
    const int wm = (wid & 1) * 64, wn = (wid >> 1) * 64;
    const uint32_t sb = smem_u32(sm);

    float acc[4][8][4];
    #pragma unroll
    for (int i = 0; i < 4; i++)
        #pragma unroll
        for (int j = 0; j < 8; j++)
            #pragma unroll
            for (int d = 0; d < 4; d++) acc[i][j][d] = 0.f;

    auto issue = [&](int c) {
        uint32_t st = sb + (uint32_t)(c % 3) * G_STAGE;
        int k0 = c * 64;
        const __half* Ar = A + (size_t)(bm + tid) * K + k0;
        const __half* Br = Bh + (size_t)(bn + tid) * K + k0;
        #pragma unroll
        for (int s = 0; s < 8; s++) {
            uint32_t o = off64(tid, s);
            cp16(st + o,         Ar + s * 8);
            cp16(st + 16384 + o, Br + s * 8);
        }
        cp_commit();
    };

    const int NC = K / 64;
    issue(0);
    issue(1);

    for (int c = 0; c < NC; c++) {
        if (c + 1 < NC) cp_wait<1>(); else cp_wait<0>();
        __syncthreads();
        uint32_t st = sb + (uint32_t)(c % 3) * G_STAGE;
        #pragma unroll
        for (int ks = 0; ks < 4; ks++) {
            uint32_t a[16];
            #pragma unroll
            for (int mt = 0; mt < 4; mt++) {
                int row = wm + mt * 16 + (lane & 7) + ((lane >> 3) & 1) * 8;
                int seg = ks * 2 + (lane >> 4);
                ldm_x4(a + mt * 4, st + off64(row, seg));
            }
            uint32_t bh[16];
            #pragma unroll
            for (int ntp = 0; ntp < 4; ntp++) {
                int row = wn + ntp * 16 + (lane & 7) + ((lane >> 4) & 1) * 8;
                int seg = ks * 2 + ((lane >> 3) & 1);
                ldm_x4(bh + ntp * 4, st + 16384 + off64(row, seg));
            }
            #pragma unroll
            for (int ntp = 0; ntp < 4; ntp++)
                #pragma unroll
                for (int half = 0; half < 2; half++)
                    #pragma unroll
                    for (int mt = 0; mt < 4; mt++)
                        mma_f16(acc[mt][ntp*2+half], a + mt*4, bh + ntp*4 + half*2);
        }
        if (c + 2 < NC) issue(c + 2);   // writes (c+2)%3 != c%3 : safe without sync
    }

    #pragma unroll
    for (int mt = 0; mt < 4; mt++) {
        int r0 = bm + wm + mt * 16 + (lane >> 2);
        #pragma unroll
        for (int nt = 0; nt < 8; nt++) {
            int col = bn + wn + nt * 8 + (lane & 3) * 2;
            float b0 = bias[col], b1 = bias[col + 1];
            float* a = acc[mt][nt];
            if (EPI == 0) {
                *(uint32_t*)(Ch + (size_t)r0 * N + col)       = pkh(a[0] + b0, a[1] + b1);
                *(uint32_t*)(Ch + (size_t)(r0 + 8) * N + col) = pkh(a[2] + b0, a[3] + b1);
            } else if (EPI == 1) {
                float v0 = a[0] + b0, v1 = a[1] + b1, v2 = a[2] + b0, v3 = a[3] + b1;
                v0 = v0 / (1.f + __expf(-v0));
                v1 = v1 / (1.f + __expf(-v1));
                v2 = v2 / (1.f + __expf(-v2));
                v3 = v3 / (1.f + __expf(-v3));
                *(uint32_t*)(Ch + (size_t)r0 * N + col)       = pkh(v0, v1);
                *(uint32_t*)(Ch + (size_t)(r0 + 8) * N + col) = pkh(v2, v3);
            } else {
                float2 p0, p1;
                float2 rr0 = *(const float2*)(res + (size_t)r0 * N + col);
                float2 rr1 = *(const float2*)(res + (size_t)(r0 + 8) * N + col);
                p0.x = a[0] + b0 + rr0.x; p0.y = a[1] + b1 + rr0.y;
                p1.x = a[2] + b0 + rr1.x; p1.y = a[3] + b1 + rr1.y;
                *(float2*)(C + (size_t)r0 * N + col) = p0;
                *(float2*)(C + (size_t)(r0 + 8) * N + col) = p1;
            }
        }
    }
}

// ---------------- Flash attention via mma.sync (fp16) ----------------
// grid: (SEQ/64, NH, B); 128 thr (4 warps, 16 q-rows each), 4 CTAs/SM.
// Scores in log2 units -> exp2f softmax; skip-rescale ballot.
// smem: Q 8K @0; KV 3 stages @8192 stride 16384 (lookahead-2, single sync): K, V(+8192)
static constexpr int A_SMEM = 8192 + 3 * 16384;   // 57344

__global__ void __launch_bounds__(128, 4)
attn_mma(const __half* __restrict__ qkvh, float* __restrict__ out)
{
    extern __shared__ char sm[];
    const int tid = threadIdx.x;
    const int wid = tid >> 5, lane = tid & 31;
    const int h = blockIdx.y, b = blockIdx.z;
    const int tok0 = b * SEQ + blockIdx.x * 64;
    const uint32_t sb = smem_u32(sm);

    // group 0: Q (64 rows x 128B)
    {
        int r = tid >> 1;
        size_t qrow = (size_t)(tok0 + r) * NQKV + h * HD;
        #pragma unroll
        for (int j = 0; j < 4; j++) {
            int s = (tid & 1) * 4 + j;
            cp16(sb + off64(r, s), qkvh + qrow + s * 8);
        }
        cp_commit();
    }
    auto issueKV = [&](int kb) {
        uint32_t st = sb + 8192 + (uint32_t)(kb % 3) * 16384;
        int r = tid >> 1;
        size_t kvrow = (size_t)(b * SEQ + kb * 64 + r) * NQKV + h * HD;
        #pragma unroll
        for (int j = 0; j < 4; j++) {
            int s = (tid & 1) * 4 + j;
            uint32_t o = off64(r, s);
            cp16(st + o, qkvh + kvrow + 1024 + s * 8);          // K
            cp16(st + 8192 + o, qkvh + kvrow + 2048 + s * 8);   // V
        }
        cp_commit();
    };
    issueKV(0);
    issueKV(1);

    cp_wait<1>(); // Q + KV0 done
    __syncthreads();

    uint32_t qf[4][4];
    {
        int row = wid * 16 + (lane & 7) + ((lane >> 3) & 1) * 8;
        #pragma unroll
        for (int ks = 0; ks < 4; ks++) {
            int seg = ks * 2 + (lane >> 4);
            ldm_x4(qf[ks], sb + off64(row, seg));
        }
    }

    float o_acc[8][4];
    #pragma unroll
    for (int i = 0; i < 8; i++)
        #pragma unroll
        for (int d = 0; d < 4; d++) o_acc[i][d] = 0.f;
    float runA = -INFINITY, runB = -INFINITY, lA = 0.f, lB = 0.f;

    const int NKB = SEQ / 64;
    for (int kb = 0; kb < NKB; kb++) {
        if (kb > 0) {
            if (kb + 1 < NKB) cp_wait<1>(); else cp_wait<0>();
            __syncthreads();
        }
        uint32_t st = sb + 8192 + (uint32_t)(kb % 3) * 16384;
        float s[8][4];
        #pragma unroll
        for (int i = 0; i < 8; i++)
            #pragma unroll
            for (int d = 0; d < 4; d++) s[i][d] = 0.f;
        #pragma unroll
        for (int ks = 0; ks < 4; ks++) {
            uint32_t bh[16];
            #pragma unroll
            for (int ntp = 0; ntp < 4; ntp++) {
                int row = ntp * 16 + (lane & 7) + ((lane >> 4) & 1) * 8;
                int seg = ks * 2 + ((lane >> 3) & 1);
                ldm_x4(bh + ntp * 4, st + off64(row, seg));
            }
            #pragma unroll
            for (int ntp = 0; ntp < 4; ntp++)
                #pragma unroll
                for (int half = 0; half < 2; half++)
                    mma_f16(s[ntp * 2 + half], qf[ks], bh + ntp * 4 + half * 2);
        }
        float mA = -INFINITY, mB = -INFINITY;
        #pragma unroll
        for (int nt = 0; nt < 8; nt++) {
            mA = fmaxf(mA, fmaxf(s[nt][0], s[nt][1]));
            mB = fmaxf(mB, fmaxf(s[nt][2], s[nt][3]));
        }
        mA = fmaxf(mA, __shfl_xor_sync(0xffffffffu, mA, 1));
        mA = fmaxf(mA, __shfl_xor_sync(0xffffffffu, mA, 2));
        mB = fmaxf(mB, __shfl_xor_sync(0xffffffffu, mB, 1));
        mB = fmaxf(mB, __shfl_xor_sync(0xffffffffu, mB, 2));
        unsigned chg = __ballot_sync(0xffffffffu, (mA > runA) || (mB > runB));
        if (chg) {
            float nA = fmaxf(runA, mA), nB = fmaxf(runB, mB);
            float cA = exp2f(runA - nA), cB = exp2f(runB - nB);
            runA = nA; runB = nB;
            lA *= cA; lB *= cB;
            #pragma unroll
            for (int nt = 0; nt < 8; nt++) {
                o_acc[nt][0] *= cA; o_acc[nt][1] *= cA;
                o_acc[nt][2] *= cB; o_acc[nt][3] *= cB;
            }
        }
        float sumA = 0.f, sumB = 0.f;
        #pragma unroll
        for (int nt = 0; nt < 8; nt++) {
            s[nt][0] = exp2f(s[nt][0] - runA); sumA += s[nt][0];
            s[nt][1] = exp2f(s[nt][1] - runA); sumA += s[nt][1];
            s[nt][2] = exp2f(s[nt][2] - runB); sumB += s[nt][2];
            s[nt][3] = exp2f(s[nt][3] - runB); sumB += s[nt][3];
        }
        lA += sumA; lB += sumB;
        uint32_t pf[4][4];
        #pragma unroll
        for (int j = 0; j < 4; j++) {
            pf[j][0] = pkh(s[2*j][0],   s[2*j][1]);
            pf[j][1] = pkh(s[2*j][2],   s[2*j][3]);
            pf[j][2] = pkh(s[2*j+1][0], s[2*j+1][1]);
            pf[j][3] = pkh(s[2*j+1][2], s[2*j+1][3]);
        }
        #pragma unroll
        for (int ks = 0; ks < 4; ks++) {
            uint32_t vb[16];
            #pragma unroll
            for (int ntp = 0; ntp < 4; ntp++) {
                int row = ks * 16 + (lane & 7) + ((lane >> 3) & 1) * 8;
                int seg = ntp * 2 + (lane >> 4);
                ldm_x4t(vb + ntp * 4, st + 8192 + off64(row, seg));
            }
            #pragma unroll
            for (int ntp = 0; ntp < 4; ntp++) {
                mma_f16(o_acc[ntp * 2 + 0], pf[ks], vb + ntp * 4 + 0);
                mma_f16(o_acc[ntp * 2 + 1], pf[ks], vb + ntp * 4 + 2);
            }
        }
        if (kb + 2 < NKB) issueKV(kb + 2);   // writes (kb+2)%3 != kb%3
    }

    lA += __shfl_xor_sync(0xffffffffu, lA, 1);
    lA += __shfl_xor_sync(0xffffffffu, lA, 2);
    lB += __shfl_xor_sync(0xffffffffu, lB, 1);
    lB += __shfl_xor_sync(0xffffffffu, lB, 2);
    float iA = 1.f / lA, iB = 1.f / lB;
    int rowA = tok0 + wid * 16 + (lane >> 2);
    #pragma unroll
    for (int nt = 0; nt < 8; nt++) {
        int col = h * HD + nt * 8 + (lane & 3) * 2;
        float2 p0 = {o_acc[nt][0] * iA, o_acc[nt][1] * iA};
        float2 p1 = {o_acc[nt][2] * iB, o_acc[nt][3] * iB};
        *(float2*)(out + (size_t)rowA * DIM + col) = p0;
        *(float2*)(out + (size_t)(rowA + 8) * DIM + col) = p1;
    }
}

// ---------------- launch ----------------
extern "C" void kernel_launch(void* const* d_in, const int* in_sizes, int n_in,
                              void* d_out, int out_size)
{
    (void)in_sizes; (void)n_in; (void)out_size;
    const float* x   = (const float*)d_in[0];
    const float* Wq  = (const float*)d_in[1];
    const float* bq  = (const float*)d_in[2];
    const float* Wk  = (const float*)d_in[3];
    const float* bk  = (const float*)d_in[4];
    const float* Wv  = (const float*)d_in[5];
    const float* bv  = (const float*)d_in[6];
    const float* g1  = (const float*)d_in[7];
    const float* b1  = (const float*)d_in[8];
    const float* g2  = (const float*)d_in[9];
    const float* b2  = (const float*)d_in[10];
    const float* W1  = (const float*)d_in[11];
    const float* bf1 = (const float*)d_in[12];
    const float* W2  = (const float*)d_in[13];
    const float* bf2 = (const float*)d_in[14];

    float *xn, *attn, *bqkv;
    cudaGetSymbolAddress((void**)&xn,   g_xn);
    cudaGetSymbolAddress((void**)&attn, g_attn);
    cudaGetSymbolAddress((void**)&bqkv, g_bqkv);

    __half *xnh, *qkvh, *hh, *f1h;
    __half *wqh, *w1h, *w2h;
    cudaGetSymbolAddress((void**)&xnh,  g_xn_h);
    cudaGetSymbolAddress((void**)&qkvh, g_qkv_h);
    cudaGetSymbolAddress((void**)&hh,   g_h_h);
    cudaGetSymbolAddress((void**)&f1h,  g_ff1_h);
    cudaGetSymbolAddress((void**)&wqh,  g_wqkv_h);
    cudaGetSymbolAddress((void**)&w1h,  g_w1_h);
    cudaGetSymbolAddress((void**)&w2h,  g_w2_h);

    cudaFuncSetAttribute((const void*)gemm_h<0>, cudaFuncAttributeMaxDynamicSharedMemorySize, G_SMEM);
    cudaFuncSetAttribute((const void*)gemm_h<1>, cudaFuncAttributeMaxDynamicSharedMemorySize, G_SMEM);
    cudaFuncSetAttribute((const void*)gemm_h<2>, cudaFuncAttributeMaxDynamicSharedMemorySize, G_SMEM);
    cudaFuncSetAttribute((const void*)attn_mma,  cudaFuncAttributeMaxDynamicSharedMemorySize, A_SMEM);

    // launch 0: QKV weight -> fp16 (+ bias concat, Q pre-scaled)
    wsplit_a<<<(WSA_TOT + 255)/256, 256>>>(Wq, Wk, Wv, bq, bk, bv, wqh, bqkv);

    // launch 1: W1/W2 -> fp16
    wsplit_b<<<(WSB_TOT + 255)/256, 256>>>(W1, W2, w1h, w2h);

    // launch 2: xn = LN(x) : fp32 + fp16
    ln_kernel<<<NTOK, 256>>>(x, nullptr, g1, b1, xn, xnh);

    // launch 3 (profiled): fused QKV projection -> fp16 [NTOK, 3072]
    dim3 gQKV(NQKV / 128, NTOK / 128);
    gemm_h<0><<<gQKV, 128, G_SMEM>>>(xnh, wqh, bqkv, nullptr, nullptr, qkvh, NQKV, DIM);

    // launch 4: attention (fp16 tensor-core flash, 4 CTAs/SM)
    attn_mma<<<dim3(SEQ / 64, NH, 2), 128, A_SMEM>>>(qkvh, attn);

    // launch 5: h = LN(attn + xn) -> fp16
    ln_kernel<<<NTOK, 256>>>(attn, xn, g2, b2, nullptr, hh);

    // launch 6: ff1 = silu(h @ W1^T + bf1) -> fp16
    dim3 gF1(DFF / 128, NTOK / 128);
    gemm_h<1><<<gF1, 128, G_SMEM>>>(hh, w1h, bf1, nullptr, nullptr, f1h, DFF, DIM);

    // launch 7: out = ff1 @ W2^T + bf2 + xn
    dim3 gF2(DIM / 128, NTOK / 128);
    gemm_h<2><<<gF2, 128, G_SMEM>>>(f1h, w2h, bf2, xn, (float*)d_out, nullptr, DIM, DFF);
}